// round 10
// baseline (speedup 1.0000x reference)
#include <cuda_runtime.h>
#include <cuda_bf16.h>
#include <stdint.h>

#define IN_F 256
#define HF   128
#define NC   64
#define MAX_NODES 10000
#define MAX_EDGES 640000
#define PAD 192   // max supported degree; Poisson(64) tail at 192 is ~1e-60

typedef unsigned long long ull;
typedef long long ll;

// ---------------- scratch (static device globals; no allocation) -------------
__device__ float g_h0[MAX_NODES * HF];
__device__ float g_h1[MAX_NODES * HF];
__device__ float g_h2[MAX_NODES * HF];
__device__ float g_mean[MAX_NODES * HF];
__device__ __nv_bfloat16 g_hb16[MAX_NODES * HF];   // bf16 copy for gather
__device__ int   g_cnt[MAX_NODES];
__device__ int   g_csr[MAX_NODES * PAD];

// Persistent split-bf16 weights
#define OFF_LIN 0
#define OFF_L1  32768
#define OFF_R1  49152
#define OFF_L2  65536
#define OFF_R2  81920
#define OFF_CLS 98304
#define TOTW    106496
__device__ __nv_bfloat16 g_Whi[TOTW];
__device__ __nv_bfloat16 g_Wlo[TOTW];

// ---------------- weight split ------------------------------------------------
__global__ void wsplit_kernel(const float* __restrict__ wlin,
                              const float* __restrict__ wl1, const float* __restrict__ wr1,
                              const float* __restrict__ wl2, const float* __restrict__ wr2,
                              const float* __restrict__ wcls) {
    int i = blockIdx.x * blockDim.x + threadIdx.x;
    if (i >= TOTW) return;
    const float* src; int off;
    if (i < OFF_L1)       { src = wlin; off = OFF_LIN; }
    else if (i < OFF_L2)  { if (i < OFF_R1) { src = wl1; off = OFF_L1; } else { src = wr1; off = OFF_R1; } }
    else if (i < OFF_CLS) { if (i < OFF_R2) { src = wl2; off = OFF_L2; } else { src = wr2; off = OFF_R2; } }
    else                  { src = wcls; off = OFF_CLS; }
    float x = src[i - off];
    __nv_bfloat16 h = __float2bfloat16_rn(x);
    g_Whi[i] = h;
    g_Wlo[i] = __float2bfloat16_rn(x - __bfloat162float(h));
}

// ---------------- scatter with inline dtype detect -----------------------------
__global__ void scatter_kernel(const void* ei, int E, int n_nodes) {
    const long long* p64 = (const long long*)ei;
    long long v = p64[threadIdx.x & 255];
    int ok = (v >= 0 && v < (long long)n_nodes) ? 1 : 0;
    int is64 = __syncthreads_and(ok);

    int e = blockIdx.x * blockDim.x + threadIdx.x;
    if (e >= E) return;
    int src, dst;
    if (is64) {
        src = (int)p64[e];
        dst = (int)p64[(ll)E + e];
    } else {
        src = ((const int*)ei)[e];
        dst = ((const int*)ei)[E + e];
    }
    int pos = atomicAdd(&g_cnt[dst], 1);
    if (pos < PAD) g_csr[dst * PAD + pos] = src;
}

// ---------------- mean aggregation over bf16 copy (warp per node, unroll 8) ---
__device__ __forceinline__ float blo(uint32_t u) { return __uint_as_float(u << 16); }
__device__ __forceinline__ float bhi(uint32_t u) { return __uint_as_float(u & 0xffff0000u); }

__global__ void __launch_bounds__(256)
agg_b16(const __nv_bfloat16* __restrict__ hb, float* __restrict__ out, int n) {
    int warp = (blockIdx.x * blockDim.x + threadIdx.x) >> 5;
    int lane = threadIdx.x & 31;
    if (warp >= n) return;
    int deg = g_cnt[warp];
    int end = deg < PAD ? deg : PAD;
    const int* lst = &g_csr[warp * PAD];
    const uint2* p = (const uint2*)hb;   // row = 32 uint2 (4 bf16 each)

    float a00=0,a01=0,a02=0,a03=0, a10=0,a11=0,a12=0,a13=0;
    float a20=0,a21=0,a22=0,a23=0, a30=0,a31=0,a32=0,a33=0;

    int e = 0;
    for (; e + 7 < end; e += 8) {
        int4 A = *(const int4*)&lst[e];        // csr rows 768B-aligned, e%8==0
        int4 B = *(const int4*)&lst[e + 4];
        uint2 v0 = p[(ll)A.x * 32 + lane];
        uint2 v1 = p[(ll)A.y * 32 + lane];
        uint2 v2 = p[(ll)A.z * 32 + lane];
        uint2 v3 = p[(ll)A.w * 32 + lane];
        uint2 v4 = p[(ll)B.x * 32 + lane];
        uint2 v5 = p[(ll)B.y * 32 + lane];
        uint2 v6 = p[(ll)B.z * 32 + lane];
        uint2 v7 = p[(ll)B.w * 32 + lane];
        a00 += blo(v0.x); a01 += bhi(v0.x); a02 += blo(v0.y); a03 += bhi(v0.y);
        a10 += blo(v1.x); a11 += bhi(v1.x); a12 += blo(v1.y); a13 += bhi(v1.y);
        a20 += blo(v2.x); a21 += bhi(v2.x); a22 += blo(v2.y); a23 += bhi(v2.y);
        a30 += blo(v3.x); a31 += bhi(v3.x); a32 += blo(v3.y); a33 += bhi(v3.y);
        a00 += blo(v4.x); a01 += bhi(v4.x); a02 += blo(v4.y); a03 += bhi(v4.y);
        a10 += blo(v5.x); a11 += bhi(v5.x); a12 += blo(v5.y); a13 += bhi(v5.y);
        a20 += blo(v6.x); a21 += bhi(v6.x); a22 += blo(v6.y); a23 += bhi(v6.y);
        a30 += blo(v7.x); a31 += bhi(v7.x); a32 += blo(v7.y); a33 += bhi(v7.y);
    }
    for (; e + 3 < end; e += 4) {
        int4 A = *(const int4*)&lst[e];
        uint2 v0 = p[(ll)A.x * 32 + lane];
        uint2 v1 = p[(ll)A.y * 32 + lane];
        uint2 v2 = p[(ll)A.z * 32 + lane];
        uint2 v3 = p[(ll)A.w * 32 + lane];
        a00 += blo(v0.x); a01 += bhi(v0.x); a02 += blo(v0.y); a03 += bhi(v0.y);
        a10 += blo(v1.x); a11 += bhi(v1.x); a12 += blo(v1.y); a13 += bhi(v1.y);
        a20 += blo(v2.x); a21 += bhi(v2.x); a22 += blo(v2.y); a23 += bhi(v2.y);
        a30 += blo(v3.x); a31 += bhi(v3.x); a32 += blo(v3.y); a33 += bhi(v3.y);
    }
    for (; e < end; e++) {
        int j0 = lst[e];
        uint2 v0 = p[(ll)j0 * 32 + lane];
        a00 += blo(v0.x); a01 += bhi(v0.x); a02 += blo(v0.y); a03 += bhi(v0.y);
    }
    float s = 1.0f / (float)(deg > 1 ? deg : 1);
    float4 r = make_float4((a00+a10+a20+a30)*s, (a01+a11+a21+a31)*s,
                           (a02+a12+a22+a32)*s, (a03+a13+a23+a33)*s);
    ((float4*)out)[(ll)warp * 32 + lane] = r;
}

// ---------------- split-bf16 MMA GEMM: BM=64, BN=64/block, ldmatrix -----------
#define MMA_BF16(c, a0,a1,a2,a3, b0,b1) \
    asm volatile("mma.sync.aligned.m16n8k16.row.col.f32.bf16.bf16.f32 " \
        "{%0,%1,%2,%3}, {%4,%5,%6,%7}, {%8,%9}, {%0,%1,%2,%3};" \
        : "+f"(c[0]), "+f"(c[1]), "+f"(c[2]), "+f"(c[3]) \
        : "r"(a0), "r"(a1), "r"(a2), "r"(a3), "r"(b0), "r"(b1))

#define LDSM_X4(r0,r1,r2,r3, addr) \
    asm volatile("ldmatrix.sync.aligned.m8n8.x4.shared.b16 {%0,%1,%2,%3}, [%4];" \
        : "=r"(r0), "=r"(r1), "=r"(r2), "=r"(r3) : "r"(addr))
#define LDSM_X2(r0,r1, addr) \
    asm volatile("ldmatrix.sync.aligned.m8n8.x2.shared.b16 {%0,%1}, [%2];" \
        : "=r"(r0), "=r"(r1) : "r"(addr))

__device__ __forceinline__ uint32_t pk_hi(float a, float b, float& ra, float& rb) {
    __nv_bfloat16 ha = __float2bfloat16_rn(a), hb = __float2bfloat16_rn(b);
    ra = a - __bfloat162float(ha);
    rb = b - __bfloat162float(hb);
    return (uint32_t)__bfloat16_as_ushort(ha) | ((uint32_t)__bfloat16_as_ushort(hb) << 16);
}
__device__ __forceinline__ uint32_t pk_lo(float a, float b) {
    return (uint32_t)__bfloat16_as_ushort(__float2bfloat16_rn(a)) |
           ((uint32_t)__bfloat16_as_ushort(__float2bfloat16_rn(b)) << 16);
}

#define PADW 20   // u32 per 32k W row (16 + 4 pad)

// KN = row stride of C; block covers 64 cols at n0 = blockIdx.y*64.
template<int KN, int KV, bool RELU_IN, bool RELU_OUT, bool HAS_BIAS, bool WB16, bool ACCUM>
__global__ void __launch_bounds__(256, 2)
mma_gemm(const float* __restrict__ A1, int woff,
         const float* __restrict__ bias, float* __restrict__ C,
         __nv_bfloat16* __restrict__ Cb16, int M) {
    const int BM   = 64;
    const int ASTR = KV / 2 + 4;
    const int ASZ  = BM * ASTR;
    const int WBUF = 64 * PADW;
    const int NCH  = KV / 32;

    extern __shared__ uint32_t sm[];
    uint32_t* As_hi = sm;
    uint32_t* As_lo = sm + ASZ;
    uint32_t* Wh    = sm + 2 * ASZ;
    uint32_t* Wl    = Wh + WBUF;

    int tid  = threadIdx.x;
    int wid  = tid >> 5;
    int lane = tid & 31;
    int g    = lane >> 2;
    int t    = lane & 3;
    int wm   = wid >> 2;
    int wn   = wid & 3;
    int m0   = blockIdx.x * BM;
    int n0   = blockIdx.y * 64;

    uint4 rh, rl;
    int w_nn = tid >> 2, w_q = tid & 3;
    auto ldregs = [&](int c) {
        int si = (n0 + w_nn) * KV + c * 32 + w_q * 8 + woff;
        rh = *(const uint4*)&g_Whi[si];
        rl = *(const uint4*)&g_Wlo[si];
    };
    auto streg = [&]() {
        *(uint4*)&Wh[w_nn * PADW + w_q * 4] = rh;
        *(uint4*)&Wl[w_nn * PADW + w_q * 4] = rl;
    };

    ldregs(0);

    // ---- A tile: load, (relu), split, store once ----------------------------
#pragma unroll
    for (int it = 0; it < BM * (KV / 4) / 256; it++) {
        int f = tid + it * 256;
        int m  = f / (KV / 4);
        int kq = f % (KV / 4);
        float4 v = make_float4(0.f, 0.f, 0.f, 0.f);
        if (m0 + m < M)
            v = *(const float4*)&A1[(ll)(m0 + m) * KV + kq * 4];
        if (RELU_IN) {
            v.x = fmaxf(v.x, 0.f); v.y = fmaxf(v.y, 0.f);
            v.z = fmaxf(v.z, 0.f); v.w = fmaxf(v.w, 0.f);
        }
        float rx, ry, rz, rw;
        uint32_t h0 = pk_hi(v.x, v.y, rx, ry);
        uint32_t h1 = pk_hi(v.z, v.w, rz, rw);
        As_hi[m * ASTR + kq * 2 + 0] = h0;
        As_hi[m * ASTR + kq * 2 + 1] = h1;
        As_lo[m * ASTR + kq * 2 + 0] = pk_lo(rx, ry);
        As_lo[m * ASTR + kq * 2 + 1] = pk_lo(rz, rw);
    }

    uint32_t aHiB = (uint32_t)__cvta_generic_to_shared(As_hi);
    uint32_t aLoB = (uint32_t)__cvta_generic_to_shared(As_lo);
    uint32_t wHiB = (uint32_t)__cvta_generic_to_shared(Wh);
    uint32_t wLoB = (uint32_t)__cvta_generic_to_shared(Wl);
    int amat = lane >> 3, ar = lane & 7;
    uint32_t aOff[2];
#pragma unroll
    for (int mf = 0; mf < 2; mf++)
        aOff[mf] = (uint32_t)((wm * 32 + mf * 16 + (amat & 1) * 8 + ar) * (ASTR * 4)
                              + (amat >> 1) * 16);
    int blx = lane & 15;
    int bmat = blx >> 3, br = blx & 7;
    uint32_t bOff[2];
#pragma unroll
    for (int nf = 0; nf < 2; nf++)
        bOff[nf] = (uint32_t)((wn * 16 + nf * 8 + br) * (PADW * 4) + bmat * 16);

    float c_[2][2][4];
#pragma unroll
    for (int i = 0; i < 2; i++)
#pragma unroll
        for (int j = 0; j < 2; j++)
#pragma unroll
            for (int q = 0; q < 4; q++) c_[i][j][q] = 0.f;

    streg();
    __syncthreads();

#pragma unroll
    for (int c = 0; c < NCH; c++) {
        if (c + 1 < NCH) ldregs(c + 1);
#pragma unroll
        for (int ko = 0; ko < 2; ko++) {
            uint32_t kbyte = (uint32_t)((c * 16 + ko * 8) * 4);
            uint32_t kwb   = (uint32_t)(ko * 8 * 4);
            uint32_t bh0[2], bh1[2], bl0[2], bl1[2];
#pragma unroll
            for (int nf = 0; nf < 2; nf++) {
                LDSM_X2(bh0[nf], bh1[nf], wHiB + bOff[nf] + kwb);
                LDSM_X2(bl0[nf], bl1[nf], wLoB + bOff[nf] + kwb);
            }
#pragma unroll
            for (int mf = 0; mf < 2; mf++) {
                uint32_t ah0, ah1, ah2, ah3, al0, al1, al2, al3;
                LDSM_X4(ah0, ah1, ah2, ah3, aHiB + aOff[mf] + kbyte);
                LDSM_X4(al0, al1, al2, al3, aLoB + aOff[mf] + kbyte);
#pragma unroll
                for (int nf = 0; nf < 2; nf++) {
                    MMA_BF16(c_[mf][nf], ah0, ah1, ah2, ah3, bh0[nf], bh1[nf]);
                    MMA_BF16(c_[mf][nf], al0, al1, al2, al3, bh0[nf], bh1[nf]);
                    MMA_BF16(c_[mf][nf], ah0, ah1, ah2, ah3, bl0[nf], bl1[nf]);
                }
            }
        }
        __syncthreads();
        if (c + 1 < NCH) {
            streg();
            __syncthreads();
        }
    }

    // ---- epilogue ------------------------------------------------------------
#pragma unroll
    for (int mf = 0; mf < 2; mf++) {
        int rowa = m0 + wm * 32 + mf * 16 + g;
        int rowb = rowa + 8;
#pragma unroll
        for (int nf = 0; nf < 2; nf++) {
            int n = n0 + wn * 16 + nf * 8 + 2 * t;
            float v0 = c_[mf][nf][0], v1 = c_[mf][nf][1];
            float v2 = c_[mf][nf][2], v3 = c_[mf][nf][3];
            if (HAS_BIAS) {
                float bb0 = bias[n], bb1 = bias[n + 1];
                v0 += bb0; v1 += bb1; v2 += bb0; v3 += bb1;
            }
            if (ACCUM) {
                if (rowa < M) {
                    float2 old = *(const float2*)&C[(ll)rowa * KN + n];
                    v0 += old.x; v1 += old.y;
                }
                if (rowb < M) {
                    float2 old = *(const float2*)&C[(ll)rowb * KN + n];
                    v2 += old.x; v3 += old.y;
                }
            }
            if (RELU_OUT) {
                v0 = fmaxf(v0, 0.f); v1 = fmaxf(v1, 0.f);
                v2 = fmaxf(v2, 0.f); v3 = fmaxf(v3, 0.f);
            }
            if (rowa < M) {
                *(float2*)&C[(ll)rowa * KN + n] = make_float2(v0, v1);
                if (WB16)
                    *(__nv_bfloat162*)&Cb16[(ll)rowa * KN + n] =
                        __nv_bfloat162(__float2bfloat16_rn(v0), __float2bfloat16_rn(v1));
            }
            if (rowb < M) {
                *(float2*)&C[(ll)rowb * KN + n] = make_float2(v2, v3);
                if (WB16)
                    *(__nv_bfloat162*)&Cb16[(ll)rowb * KN + n] =
                        __nv_bfloat162(__float2bfloat16_rn(v2), __float2bfloat16_rn(v3));
            }
        }
    }
}

static inline int smem_bytes(int KV) {
    return (2 * 64 * (KV / 2 + 4) + 2 * 64 * PADW) * 4;
}

// ---------------- launch ------------------------------------------------------
extern "C" void kernel_launch(void* const* d_in, const int* in_sizes, int n_in,
                              void* d_out, int out_size) {
    const float* x     = (const float*)d_in[0];
    const void*  ei    = d_in[1];
    const float* W_lin = (const float*)d_in[2];
    const float* b_lin = (const float*)d_in[3];
    const float* Wl1   = (const float*)d_in[4];
    const float* bl1   = (const float*)d_in[5];
    const float* Wr1   = (const float*)d_in[6];
    const float* Wl2   = (const float*)d_in[7];
    const float* bl2   = (const float*)d_in[8];
    const float* Wr2   = (const float*)d_in[9];
    const float* W_cls = (const float*)d_in[10];
    float* out = (float*)d_out;

    int n_nodes = in_sizes[0] / IN_F;
    int E       = in_sizes[1] / 2;

    float *h0, *h1, *h2, *mean;
    __nv_bfloat16* hb16;
    int* cnt;
    cudaGetSymbolAddress((void**)&h0,   g_h0);
    cudaGetSymbolAddress((void**)&h1,   g_h1);
    cudaGetSymbolAddress((void**)&h2,   g_h2);
    cudaGetSymbolAddress((void**)&mean, g_mean);
    cudaGetSymbolAddress((void**)&hb16, g_hb16);
    cudaGetSymbolAddress((void**)&cnt,  g_cnt);

    // One-time host resources for capture-forked parallel branch
    static cudaStream_t s1 = nullptr;
    static cudaEvent_t evRoot, evScat, evProj, evWr1, evWl1, evWr2;
    if (!s1) {
        cudaStreamCreateWithFlags(&s1, cudaStreamNonBlocking);
        cudaEventCreateWithFlags(&evRoot, cudaEventDisableTiming);
        cudaEventCreateWithFlags(&evScat, cudaEventDisableTiming);
        cudaEventCreateWithFlags(&evProj, cudaEventDisableTiming);
        cudaEventCreateWithFlags(&evWr1,  cudaEventDisableTiming);
        cudaEventCreateWithFlags(&evWl1,  cudaEventDisableTiming);
        cudaEventCreateWithFlags(&evWr2,  cudaEventDisableTiming);
    }

    int nb_edges = (E + 255) / 256;
    int nb_agg   = (n_nodes + 7) / 8;
    dim3 gH((n_nodes + 63) / 64, 2);   // KN=128 GEMMs
    dim3 gC((n_nodes + 63) / 64, 1);   // cls

    auto kProj = mma_gemm<HF, IN_F, false, true,  true,  true,  false>;
    auto kWr   = mma_gemm<HF, HF,   false, false, false, false, false>;
    auto kWl1  = mma_gemm<HF, HF,   false, false, true,  true,  true>;
    auto kWl2  = mma_gemm<HF, HF,   false, false, true,  false, true>;
    auto kCls  = mma_gemm<NC, HF,   true,  false, false, false, false>;
    int sProj = smem_bytes(IN_F);
    int sHF   = smem_bytes(HF);
    cudaFuncSetAttribute(kProj, cudaFuncAttributeMaxDynamicSharedMemorySize, sProj);
    cudaFuncSetAttribute(kWr,   cudaFuncAttributeMaxDynamicSharedMemorySize, sHF);
    cudaFuncSetAttribute(kWl1,  cudaFuncAttributeMaxDynamicSharedMemorySize, sHF);
    cudaFuncSetAttribute(kWl2,  cudaFuncAttributeMaxDynamicSharedMemorySize, sHF);
    cudaFuncSetAttribute(kCls,  cudaFuncAttributeMaxDynamicSharedMemorySize, sHF);

    // ---- fork: s1 builds CSR while s0 splits weights + runs proj ------------
    cudaEventRecord(evRoot, 0);
    cudaStreamWaitEvent(s1, evRoot, 0);

    cudaMemsetAsync(cnt, 0, n_nodes * sizeof(int), s1);
    scatter_kernel<<<nb_edges, 256, 0, s1>>>(ei, E, n_nodes);
    cudaEventRecord(evScat, s1);

    wsplit_kernel<<<(TOTW + 255) / 256, 256>>>(W_lin, Wl1, Wr1, Wl2, Wr2, W_cls);
    kProj<<<gH, 256, sProj>>>(x, OFF_LIN, b_lin, h0, hb16, n_nodes);
    cudaEventRecord(evProj, 0);

    // ---- layer 1: agg(s0) || h0@Wr1(s1), then mean@Wl1 += --------------------
    cudaStreamWaitEvent(s1, evProj, 0);
    kWr<<<gH, 256, sHF, s1>>>(h0, OFF_R1, nullptr, h1, nullptr, n_nodes);
    cudaEventRecord(evWr1, s1);

    cudaStreamWaitEvent(0, evScat, 0);
    agg_b16<<<nb_agg, 256>>>(hb16, mean, n_nodes);
    cudaStreamWaitEvent(0, evWr1, 0);
    kWl1<<<gH, 256, sHF>>>(mean, OFF_L1, bl1, h1, hb16, n_nodes);
    cudaEventRecord(evWl1, 0);

    // ---- layer 2: agg(s0) || h1@Wr2(s1), then mean@Wl2 += --------------------
    cudaStreamWaitEvent(s1, evWl1, 0);
    kWr<<<gH, 256, sHF, s1>>>(h1, OFF_R2, nullptr, h2, nullptr, n_nodes);
    cudaEventRecord(evWr2, s1);

    agg_b16<<<nb_agg, 256>>>(hb16, mean, n_nodes);
    cudaStreamWaitEvent(0, evWr2, 0);
    kWl2<<<gH, 256, sHF>>>(mean, OFF_L2, bl2, h2, nullptr, n_nodes);

    // ---- classifier ----------------------------------------------------------
    kCls<<<gC, 256, sHF>>>(h2, OFF_CLS, nullptr, out, nullptr, n_nodes);
}

// round 11
// speedup vs baseline: 1.0189x; 1.0189x over previous
#include <cuda_runtime.h>
#include <cuda_bf16.h>
#include <stdint.h>

#define IN_F 256
#define HF   128
#define NC   64
#define MAX_NODES 10000
#define MAX_EDGES 640000
#define PAD 192   // max supported degree; Poisson(64) tail at 192 is ~1e-60

typedef unsigned long long ull;
typedef long long ll;

// ---------------- scratch (static device globals; no allocation) -------------
__device__ float g_h0[MAX_NODES * HF];
__device__ float g_h1[MAX_NODES * HF];
__device__ float g_h2[MAX_NODES * HF];
__device__ float g_mean[MAX_NODES * HF];
__device__ __nv_bfloat16 g_hb16[MAX_NODES * HF];   // bf16 copy for gather
__device__ int   g_cnt[MAX_NODES];
__device__ int   g_csr[MAX_NODES * PAD];

// Persistent split-bf16 weights
#define OFF_LIN 0
#define OFF_L1  32768
#define OFF_R1  49152
#define OFF_L2  65536
#define OFF_R2  81920
#define OFF_CLS 98304
#define TOTW    106496
__device__ __nv_bfloat16 g_Whi[TOTW];
__device__ __nv_bfloat16 g_Wlo[TOTW];

// ---------------- init: zero counters + split weights --------------------------
__global__ void init_kernel(const float* __restrict__ wlin,
                            const float* __restrict__ wl1, const float* __restrict__ wr1,
                            const float* __restrict__ wl2, const float* __restrict__ wr2,
                            const float* __restrict__ wcls, int n_nodes) {
    int i = blockIdx.x * blockDim.x + threadIdx.x;
    if (i < n_nodes) g_cnt[i] = 0;
    if (i >= TOTW) return;
    const float* src; int off;
    if (i < OFF_L1)       { src = wlin; off = OFF_LIN; }
    else if (i < OFF_L2)  { if (i < OFF_R1) { src = wl1; off = OFF_L1; } else { src = wr1; off = OFF_R1; } }
    else if (i < OFF_CLS) { if (i < OFF_R2) { src = wl2; off = OFF_L2; } else { src = wr2; off = OFF_R2; } }
    else                  { src = wcls; off = OFF_CLS; }
    float x = src[i - off];
    __nv_bfloat16 h = __float2bfloat16_rn(x);
    g_Whi[i] = h;
    g_Wlo[i] = __float2bfloat16_rn(x - __bfloat162float(h));
}

// ---------------- scatter with inline dtype detect -----------------------------
__global__ void scatter_kernel(const void* ei, int E, int n_nodes) {
    const long long* p64 = (const long long*)ei;
    long long v = p64[threadIdx.x & 255];
    int ok = (v >= 0 && v < (long long)n_nodes) ? 1 : 0;
    int is64 = __syncthreads_and(ok);

    int e = blockIdx.x * blockDim.x + threadIdx.x;
    if (e >= E) return;
    int src, dst;
    if (is64) {
        src = (int)p64[e];
        dst = (int)p64[(ll)E + e];
    } else {
        src = ((const int*)ei)[e];
        dst = ((const int*)ei)[E + e];
    }
    int pos = atomicAdd(&g_cnt[dst], 1);
    if (pos < PAD) g_csr[dst * PAD + pos] = src;
}

// ---------------- mean aggregation over bf16 copy (warp per node, unroll 8) ---
__device__ __forceinline__ float blo(uint32_t u) { return __uint_as_float(u << 16); }
__device__ __forceinline__ float bhi(uint32_t u) { return __uint_as_float(u & 0xffff0000u); }

__global__ void __launch_bounds__(256)
agg_b16(const __nv_bfloat16* __restrict__ hb, float* __restrict__ out, int n) {
    int warp = (blockIdx.x * blockDim.x + threadIdx.x) >> 5;
    int lane = threadIdx.x & 31;
    if (warp >= n) return;
    int deg = g_cnt[warp];
    int end = deg < PAD ? deg : PAD;
    const int* lst = &g_csr[warp * PAD];
    const uint2* p = (const uint2*)hb;   // row = 32 uint2 (4 bf16 each)

    float a00=0,a01=0,a02=0,a03=0, a10=0,a11=0,a12=0,a13=0;
    float a20=0,a21=0,a22=0,a23=0, a30=0,a31=0,a32=0,a33=0;

    int e = 0;
    for (; e + 7 < end; e += 8) {
        int4 A = *(const int4*)&lst[e];        // csr rows 768B-aligned, e%8==0
        int4 B = *(const int4*)&lst[e + 4];
        uint2 v0 = p[(ll)A.x * 32 + lane];
        uint2 v1 = p[(ll)A.y * 32 + lane];
        uint2 v2 = p[(ll)A.z * 32 + lane];
        uint2 v3 = p[(ll)A.w * 32 + lane];
        uint2 v4 = p[(ll)B.x * 32 + lane];
        uint2 v5 = p[(ll)B.y * 32 + lane];
        uint2 v6 = p[(ll)B.z * 32 + lane];
        uint2 v7 = p[(ll)B.w * 32 + lane];
        a00 += blo(v0.x); a01 += bhi(v0.x); a02 += blo(v0.y); a03 += bhi(v0.y);
        a10 += blo(v1.x); a11 += bhi(v1.x); a12 += blo(v1.y); a13 += bhi(v1.y);
        a20 += blo(v2.x); a21 += bhi(v2.x); a22 += blo(v2.y); a23 += bhi(v2.y);
        a30 += blo(v3.x); a31 += bhi(v3.x); a32 += blo(v3.y); a33 += bhi(v3.y);
        a00 += blo(v4.x); a01 += bhi(v4.x); a02 += blo(v4.y); a03 += bhi(v4.y);
        a10 += blo(v5.x); a11 += bhi(v5.x); a12 += blo(v5.y); a13 += bhi(v5.y);
        a20 += blo(v6.x); a21 += bhi(v6.x); a22 += blo(v6.y); a23 += bhi(v6.y);
        a30 += blo(v7.x); a31 += bhi(v7.x); a32 += blo(v7.y); a33 += bhi(v7.y);
    }
    for (; e + 3 < end; e += 4) {
        int4 A = *(const int4*)&lst[e];
        uint2 v0 = p[(ll)A.x * 32 + lane];
        uint2 v1 = p[(ll)A.y * 32 + lane];
        uint2 v2 = p[(ll)A.z * 32 + lane];
        uint2 v3 = p[(ll)A.w * 32 + lane];
        a00 += blo(v0.x); a01 += bhi(v0.x); a02 += blo(v0.y); a03 += bhi(v0.y);
        a10 += blo(v1.x); a11 += bhi(v1.x); a12 += blo(v1.y); a13 += bhi(v1.y);
        a20 += blo(v2.x); a21 += bhi(v2.x); a22 += blo(v2.y); a23 += bhi(v2.y);
        a30 += blo(v3.x); a31 += bhi(v3.x); a32 += blo(v3.y); a33 += bhi(v3.y);
    }
    for (; e < end; e++) {
        int j0 = lst[e];
        uint2 v0 = p[(ll)j0 * 32 + lane];
        a00 += blo(v0.x); a01 += bhi(v0.x); a02 += blo(v0.y); a03 += bhi(v0.y);
    }
    float s = 1.0f / (float)(deg > 1 ? deg : 1);
    float4 r = make_float4((a00+a10+a20+a30)*s, (a01+a11+a21+a31)*s,
                           (a02+a12+a22+a32)*s, (a03+a13+a23+a33)*s);
    ((float4*)out)[(ll)warp * 32 + lane] = r;
}

// ---------------- split-bf16 MMA GEMM: BM=64, BN=64 per block, ldmatrix -------
#define MMA_BF16(c, a0,a1,a2,a3, b0,b1) \
    asm volatile("mma.sync.aligned.m16n8k16.row.col.f32.bf16.bf16.f32 " \
        "{%0,%1,%2,%3}, {%4,%5,%6,%7}, {%8,%9}, {%0,%1,%2,%3};" \
        : "+f"(c[0]), "+f"(c[1]), "+f"(c[2]), "+f"(c[3]) \
        : "r"(a0), "r"(a1), "r"(a2), "r"(a3), "r"(b0), "r"(b1))

#define LDSM_X4(r0,r1,r2,r3, addr) \
    asm volatile("ldmatrix.sync.aligned.m8n8.x4.shared.b16 {%0,%1,%2,%3}, [%4];" \
        : "=r"(r0), "=r"(r1), "=r"(r2), "=r"(r3) : "r"(addr))
#define LDSM_X2(r0,r1, addr) \
    asm volatile("ldmatrix.sync.aligned.m8n8.x2.shared.b16 {%0,%1}, [%2];" \
        : "=r"(r0), "=r"(r1) : "r"(addr))

__device__ __forceinline__ uint32_t pk_hi(float a, float b, float& ra, float& rb) {
    __nv_bfloat16 ha = __float2bfloat16_rn(a), hb = __float2bfloat16_rn(b);
    ra = a - __bfloat162float(ha);
    rb = b - __bfloat162float(hb);
    return (uint32_t)__bfloat16_as_ushort(ha) | ((uint32_t)__bfloat16_as_ushort(hb) << 16);
}
__device__ __forceinline__ uint32_t pk_lo(float a, float b) {
    return (uint32_t)__bfloat16_as_ushort(__float2bfloat16_rn(a)) |
           ((uint32_t)__bfloat16_as_ushort(__float2bfloat16_rn(b)) << 16);
}

#define PADW 20   // u32 per 32k W row (16 + 4 pad)

// KN = full output width (row stride of C); block covers 64 columns at n0.
template<int KN, int KV, bool DUAL, bool RELU_IN, bool RELU_OUT, bool HAS_BIAS, bool WB16>
__global__ void __launch_bounds__(256, 2)
mma_gemm(const float* __restrict__ A1, const float* __restrict__ A2,
         int woff1, int woff2,
         const float* __restrict__ bias, float* __restrict__ C,
         __nv_bfloat16* __restrict__ Cb16, int M) {
    const int BM   = 64;
    const int ASTR = KV / 2 + 4;          // u32 per A row
    const int ASZ  = BM * ASTR;
    const int WBUF = 64 * PADW;
    const int NCH  = KV / 32;
    const int KA   = DUAL ? KV / 2 : KV;

    extern __shared__ uint32_t sm[];
    uint32_t* As_hi = sm;
    uint32_t* As_lo = sm + ASZ;
    uint32_t* Wh    = sm + 2 * ASZ;
    uint32_t* Wl    = Wh + WBUF;

    int tid  = threadIdx.x;
    int wid  = tid >> 5;
    int lane = tid & 31;
    int g    = lane >> 2;
    int t    = lane & 3;
    int wm   = wid >> 2;   // 0..1 : 32 rows each
    int wn   = wid & 3;    // 0..3 : 16 cols each
    int m0   = blockIdx.x * BM;
    int n0   = blockIdx.y * 64;

    // W chunk register prefetch (1 uint4 pair per thread covers 64x32 chunk)
    uint4 rh, rl;
    int w_nn = tid >> 2, w_q = tid & 3;
    auto ldregs = [&](int c) {
        int k = c * 32 + w_q * 8;
        int wo = woff1, kk = k;
        if (DUAL && k >= KV / 2) { wo = woff2; kk = k - KV / 2; }
        int si = (n0 + w_nn) * KA + kk + wo;
        rh = *(const uint4*)&g_Whi[si];
        rl = *(const uint4*)&g_Wlo[si];
    };
    auto streg = [&]() {
        *(uint4*)&Wh[w_nn * PADW + w_q * 4] = rh;
        *(uint4*)&Wl[w_nn * PADW + w_q * 4] = rl;
    };

    ldregs(0);

    // ---- A tile: load, (relu), split, store once ----------------------------
#pragma unroll
    for (int it = 0; it < BM * (KV / 4) / 256; it++) {
        int f = tid + it * 256;
        int m  = f / (KV / 4);
        int kq = f % (KV / 4);
        int k  = kq * 4;
        const float* src = A1; int kk = k;
        if (DUAL && k >= KV / 2) { src = A2; kk = k - KV / 2; }
        float4 v = make_float4(0.f, 0.f, 0.f, 0.f);
        if (m0 + m < M)
            v = *(const float4*)&src[(ll)(m0 + m) * KA + kk];
        if (RELU_IN) {
            v.x = fmaxf(v.x, 0.f); v.y = fmaxf(v.y, 0.f);
            v.z = fmaxf(v.z, 0.f); v.w = fmaxf(v.w, 0.f);
        }
        float rx, ry, rz, rw;
        uint32_t h0 = pk_hi(v.x, v.y, rx, ry);
        uint32_t h1 = pk_hi(v.z, v.w, rz, rw);
        As_hi[m * ASTR + kq * 2 + 0] = h0;
        As_hi[m * ASTR + kq * 2 + 1] = h1;
        As_lo[m * ASTR + kq * 2 + 0] = pk_lo(rx, ry);
        As_lo[m * ASTR + kq * 2 + 1] = pk_lo(rz, rw);
    }

    // ldmatrix per-thread address precomputation
    uint32_t aHiB = (uint32_t)__cvta_generic_to_shared(As_hi);
    uint32_t aLoB = (uint32_t)__cvta_generic_to_shared(As_lo);
    uint32_t wHiB = (uint32_t)__cvta_generic_to_shared(Wh);
    uint32_t wLoB = (uint32_t)__cvta_generic_to_shared(Wl);
    int amat = lane >> 3, ar = lane & 7;
    uint32_t aOff[2];
#pragma unroll
    for (int mf = 0; mf < 2; mf++)
        aOff[mf] = (uint32_t)((wm * 32 + mf * 16 + (amat & 1) * 8 + ar) * (ASTR * 4)
                              + (amat >> 1) * 16);
    int blx = lane & 15;
    int bmat = blx >> 3, br = blx & 7;
    uint32_t bOff[2];
#pragma unroll
    for (int nf = 0; nf < 2; nf++)
        bOff[nf] = (uint32_t)((wn * 16 + nf * 8 + br) * (PADW * 4) + bmat * 16);

    float c_[2][2][4];
#pragma unroll
    for (int i = 0; i < 2; i++)
#pragma unroll
        for (int j = 0; j < 2; j++)
#pragma unroll
            for (int q = 0; q < 4; q++) c_[i][j][q] = 0.f;

    streg();
    __syncthreads();

#pragma unroll
    for (int c = 0; c < NCH; c++) {
        if (c + 1 < NCH) ldregs(c + 1);
#pragma unroll
        for (int ko = 0; ko < 2; ko++) {
            uint32_t kbyte = (uint32_t)((c * 16 + ko * 8) * 4);
            uint32_t kwb   = (uint32_t)(ko * 8 * 4);
            uint32_t bh0[2], bh1[2], bl0[2], bl1[2];
#pragma unroll
            for (int nf = 0; nf < 2; nf++) {
                LDSM_X2(bh0[nf], bh1[nf], wHiB + bOff[nf] + kwb);
                LDSM_X2(bl0[nf], bl1[nf], wLoB + bOff[nf] + kwb);
            }
#pragma unroll
            for (int mf = 0; mf < 2; mf++) {
                uint32_t ah0, ah1, ah2, ah3, al0, al1, al2, al3;
                LDSM_X4(ah0, ah1, ah2, ah3, aHiB + aOff[mf] + kbyte);
                LDSM_X4(al0, al1, al2, al3, aLoB + aOff[mf] + kbyte);
#pragma unroll
                for (int nf = 0; nf < 2; nf++) {
                    MMA_BF16(c_[mf][nf], ah0, ah1, ah2, ah3, bh0[nf], bh1[nf]);
                    MMA_BF16(c_[mf][nf], al0, al1, al2, al3, bh0[nf], bh1[nf]);
                    MMA_BF16(c_[mf][nf], ah0, ah1, ah2, ah3, bl0[nf], bl1[nf]);
                }
            }
        }
        __syncthreads();
        if (c + 1 < NCH) {
            streg();
            __syncthreads();
        }
    }

    // ---- epilogue ------------------------------------------------------------
#pragma unroll
    for (int mf = 0; mf < 2; mf++) {
        int rowa = m0 + wm * 32 + mf * 16 + g;
        int rowb = rowa + 8;
#pragma unroll
        for (int nf = 0; nf < 2; nf++) {
            int n = n0 + wn * 16 + nf * 8 + 2 * t;
            float v0 = c_[mf][nf][0], v1 = c_[mf][nf][1];
            float v2 = c_[mf][nf][2], v3 = c_[mf][nf][3];
            if (HAS_BIAS) {
                float bb0 = bias[n], bb1 = bias[n + 1];
                v0 += bb0; v1 += bb1; v2 += bb0; v3 += bb1;
            }
            if (RELU_OUT) {
                v0 = fmaxf(v0, 0.f); v1 = fmaxf(v1, 0.f);
                v2 = fmaxf(v2, 0.f); v3 = fmaxf(v3, 0.f);
            }
            if (rowa < M) {
                *(float2*)&C[(ll)rowa * KN + n] = make_float2(v0, v1);
                if (WB16)
                    *(__nv_bfloat162*)&Cb16[(ll)rowa * KN + n] =
                        __nv_bfloat162(__float2bfloat16_rn(v0), __float2bfloat16_rn(v1));
            }
            if (rowb < M) {
                *(float2*)&C[(ll)rowb * KN + n] = make_float2(v2, v3);
                if (WB16)
                    *(__nv_bfloat162*)&Cb16[(ll)rowb * KN + n] =
                        __nv_bfloat162(__float2bfloat16_rn(v2), __float2bfloat16_rn(v3));
            }
        }
    }
}

static inline int smem_bytes(int KV) {
    return (2 * 64 * (KV / 2 + 4) + 2 * 64 * PADW) * 4;
}

// ---------------- launch ------------------------------------------------------
extern "C" void kernel_launch(void* const* d_in, const int* in_sizes, int n_in,
                              void* d_out, int out_size) {
    const float* x     = (const float*)d_in[0];
    const void*  ei    = d_in[1];
    const float* W_lin = (const float*)d_in[2];
    const float* b_lin = (const float*)d_in[3];
    const float* Wl1   = (const float*)d_in[4];
    const float* bl1   = (const float*)d_in[5];
    const float* Wr1   = (const float*)d_in[6];
    const float* Wl2   = (const float*)d_in[7];
    const float* bl2   = (const float*)d_in[8];
    const float* Wr2   = (const float*)d_in[9];
    const float* W_cls = (const float*)d_in[10];
    float* out = (float*)d_out;

    int n_nodes = in_sizes[0] / IN_F;
    int E       = in_sizes[1] / 2;

    float *h0, *h1, *h2, *mean;
    __nv_bfloat16* hb16;
    cudaGetSymbolAddress((void**)&h0,   g_h0);
    cudaGetSymbolAddress((void**)&h1,   g_h1);
    cudaGetSymbolAddress((void**)&h2,   g_h2);
    cudaGetSymbolAddress((void**)&mean, g_mean);
    cudaGetSymbolAddress((void**)&hb16, g_hb16);

    int nb_edges = (E + 255) / 256;
    int nb_agg   = (n_nodes + 7) / 8;
    dim3 gH((n_nodes + 63) / 64, 2);   // 157 x 2 = 314 blocks (KN=128)
    dim3 gC((n_nodes + 63) / 64, 1);   // cls (KN=64)

    auto kProj = mma_gemm<HF, 256, false, false, true,  true,  true>;
    auto kSg1  = mma_gemm<HF, 256, true,  false, false, true,  true>;
    auto kSg2  = mma_gemm<HF, 256, true,  false, false, true,  false>;
    auto kCls  = mma_gemm<NC, 128, false, true,  false, false, false>;
    int sBig = smem_bytes(256);
    int sCls = smem_bytes(128);
    cudaFuncSetAttribute(kProj, cudaFuncAttributeMaxDynamicSharedMemorySize, sBig);
    cudaFuncSetAttribute(kSg1,  cudaFuncAttributeMaxDynamicSharedMemorySize, sBig);
    cudaFuncSetAttribute(kSg2,  cudaFuncAttributeMaxDynamicSharedMemorySize, sBig);
    cudaFuncSetAttribute(kCls,  cudaFuncAttributeMaxDynamicSharedMemorySize, sCls);

    // init (cnt zero + weight split), then CSR scatter w/ inline dtype detect
    init_kernel<<<(TOTW + 255) / 256, 256>>>(W_lin, Wl1, Wr1, Wl2, Wr2, W_cls, n_nodes);
    scatter_kernel<<<nb_edges, 256>>>(ei, E, n_nodes);

    // h0 = relu(x @ W_lin^T + b_lin) (+ bf16 copy)
    kProj<<<gH, 256, sBig>>>(x, nullptr, OFF_LIN, 0, b_lin, h0, hb16, n_nodes);

    // sage1: mean = agg(h0_b16); h1 = [mean|h0] @ [[Wl1];[Wr1]]^T + bl1 (+ b16)
    agg_b16<<<nb_agg, 256>>>(hb16, mean, n_nodes);
    kSg1<<<gH, 256, sBig>>>(mean, h0, OFF_L1, OFF_R1, bl1, h1, hb16, n_nodes);

    // sage2: mean = agg(h1_b16); h2 = [mean|h1] @ [[Wl2];[Wr2]]^T + bl2
    agg_b16<<<nb_agg, 256>>>(hb16, mean, n_nodes);
    kSg2<<<gH, 256, sBig>>>(mean, h1, OFF_L2, OFF_R2, bl2, h2, nullptr, n_nodes);

    // out = relu(h2) @ W_cls^T
    kCls<<<gC, 256, sCls>>>(h2, nullptr, OFF_CLS, 0, nullptr, out, nullptr, n_nodes);
}